// round 17
// baseline (speedup 1.0000x reference)
#include <cuda_runtime.h>
#include <math.h>
#include <stdint.h>

#define N_SEQ   2048
#define SEQ_LEN 24
#define SEQ_C   9
#define N_FILT  32
#define KM      16
#define HID     128
#define NCLS    10

#define MLP_SEQS 16   // sequences per MLP block -> 128 blocks

__device__ float g_kT[KM * SEQ_C * N_FILT];   // kernels transposed AND scaled by -2: [i][c][f]
__device__ float g_knorm[KM * N_FILT];        // |kernel row|^2 (unscaled):  [i][f]
__device__ float g_feats[N_SEQ * N_FILT];     // DTW features
__device__ int   g_flag;                      // prep-done counter (monotonic across replays)

__device__ __forceinline__ void cp_async16(uint32_t saddr, const void* gptr) {
    asm volatile("cp.async.cg.shared.global [%0], [%1], 16;" :: "r"(saddr), "l"(gptr));
}
__device__ __forceinline__ void cp_async_commit() {
    asm volatile("cp.async.commit_group;");
}
__device__ __forceinline__ void cp_async_wait_all() {
    asm volatile("cp.async.wait_group 0;");
}
__device__ __forceinline__ void grid_dep_wait() {
    asm volatile("griddepcontrol.wait;" ::: "memory");
}

// ---------------------------------------------------------------------------
// Kernel A: prep + DTW fused in one grid. (r16 verbatim, FROZEN)
//   blocks 0..15       : prep-only (kernel-row i = blockIdx.x), then exit.
//   blocks 16..16+2047 : DTW for sequence s = blockIdx.x - 16.
// ---------------------------------------------------------------------------
__global__ __launch_bounds__(32) void dtw_kernel(const float* __restrict__ x,
                                                 const float* __restrict__ kernels) {
    if (blockIdx.x < KM) {
        const int i = blockIdx.x;
        const int f = threadIdx.x;
        float kv[SEQ_C];
        float nrm = 0.f;
#pragma unroll
        for (int c = 0; c < SEQ_C; ++c)
            kv[c] = kernels[f * (KM * SEQ_C) + i * SEQ_C + c];
#pragma unroll
        for (int c = 0; c < SEQ_C; ++c) {
            g_kT[(i * SEQ_C + c) * N_FILT + f] = -2.f * kv[c];
            nrm = fmaf(kv[c], kv[c], nrm);
        }
        g_knorm[i * N_FILT + f] = nrm;
        __threadfence();
        __syncwarp();
        if (f == 0) atomicAdd(&g_flag, 1);
        return;
    }

    __shared__ float seqS[SEQ_LEN * SEQ_C];
    __shared__ float snormS[SEQ_LEN];

    const int s = blockIdx.x - KM;
    const int f = threadIdx.x;

    const float* xs = x + s * (SEQ_LEN * SEQ_C);
    for (int t = f; t < SEQ_LEN * SEQ_C; t += 32) seqS[t] = xs[t];
    __syncthreads();

    if (f < SEQ_LEN) {
        float a = 0.f;
#pragma unroll
        for (int c = 0; c < SEQ_C; ++c) {
            float v = seqS[f * SEQ_C + c];
            a = fmaf(v, v, a);
        }
        snormS[f] = a;
    }
    __syncthreads();

    if (f == 0) {
        while (atomicAdd(&g_flag, 0) < KM) { __nanosleep(64); }
    }
    __syncthreads();

    float Dp[SEQ_LEN];

    {
        float k0[SEQ_C];
#pragma unroll
        for (int c = 0; c < SEQ_C; ++c) k0[c] = g_kT[c * N_FILT + f];
        float kn = g_knorm[f];
        float run = 0.f;
#pragma unroll
        for (int j = 0; j < SEQ_LEN; ++j) {
            float acc = kn + snormS[j];
#pragma unroll
            for (int c = 0; c < SEQ_C; ++c) acc = fmaf(k0[c], seqS[j * SEQ_C + c], acc);
            run = (j == 0) ? acc : (run + acc);
            Dp[j] = run;
        }
    }

    const float INF = __int_as_float(0x7f800000);

    for (int sw = 0; sw < 3; ++sw) {
        const int i0 = 1 + sw * 5;
        float kr[5][SEQ_C], knr[5], left[5];
#pragma unroll
        for (int r = 0; r < 5; ++r) {
#pragma unroll
            for (int c = 0; c < SEQ_C; ++c)
                kr[r][c] = g_kT[((i0 + r) * SEQ_C + c) * N_FILT + f];
            knr[r] = g_knorm[(i0 + r) * N_FILT + f];
            left[r] = INF;
        }
        float diagc = INF;
#pragma unroll
        for (int j = 0; j < SEQ_LEN; ++j) {
            float sv[SEQ_C];
#pragma unroll
            for (int c = 0; c < SEQ_C; ++c) sv[c] = seqS[j * SEQ_C + c];
            float sn = snormS[j];
            float up = Dp[j];
            float oldup = up;
            float diag = diagc;
#pragma unroll
            for (int r = 0; r < 5; ++r) {
                float acc = knr[r] + sn;
#pragma unroll
                for (int c = 0; c < SEQ_C; ++c) acc = fmaf(kr[r][c], sv[c], acc);
                float best = fminf(left[r], fminf(up, diag));
                float d = acc + best;
                diag = left[r];
                left[r] = d;
                up = d;
            }
            Dp[j] = up;
            diagc = oldup;
        }
    }

    g_feats[s * N_FILT + f] = Dp[SEQ_LEN - 1];
}

// ---------------------------------------------------------------------------
// Kernel B: MLP, 16 seqs/block, 128 threads (thread = hidden unit), 16
// accumulators per thread -> 16 independent FMAs per W2 shared load.
// Max FMA density + ILP at low occupancy. PDL preamble unchanged.
// ---------------------------------------------------------------------------
__global__ __launch_bounds__(128) void mlp_kernel(
    const float* __restrict__ W1, const float* __restrict__ b1,
    const float* __restrict__ W2, const float* __restrict__ b2,
    const float* __restrict__ Wl, const float* __restrict__ bl,
    float* __restrict__ out) {
    extern __shared__ float smem[];
    float* W2s = smem;                        // [128*128]          64KB
    float* t1S = W2s + HID * HID;             // [h][16]             8KB
    float* t2S = t1S + HID * MLP_SEQS;        // [h][16]             8KB
    float* fSt = t2S + HID * MLP_SEQS;        // [filter][16]        2KB
    float* WlS = fSt + N_FILT * MLP_SEQS;     // [c][h] transposed   5KB

    const int t  = threadIdx.x;               // 0..127 = hidden unit
    const int s0 = blockIdx.x * MLP_SEQS;

    // Independent of DTW output: prefetch W2 (32 float4/thread), stage Wl.
    {
        uint32_t base = (uint32_t)__cvta_generic_to_shared(W2s);
        const float4* g = reinterpret_cast<const float4*>(W2);
#pragma unroll
        for (int i = 0; i < 32; ++i) {
            int e = t + i * 128;
            cp_async16(base + e * 16, g + e);
        }
        cp_async_commit();
    }
    for (int i = t; i < HID * NCLS; i += 128) {
        int h = i / NCLS, c = i - h * NCLS;
        WlS[c * HID + h] = Wl[i];
    }

    grid_dep_wait();

    // Stage features transposed [filter][seq]: 512 elements, 4 per thread.
#pragma unroll
    for (int i = t; i < N_FILT * MLP_SEQS; i += 128) {
        int sq = i >> 5, ff = i & 31;
        fSt[ff * MLP_SEQS + sq] = g_feats[s0 * N_FILT + i];
    }
    __syncthreads();

    // ---- Layer 1 (32 -> 128): 16 accumulators per thread ----
    {
        float b = b1[t];
        float a[MLP_SEQS];
#pragma unroll
        for (int q = 0; q < MLP_SEQS; ++q) a[q] = b;
#pragma unroll 4
        for (int ff = 0; ff < N_FILT; ++ff) {
            float w = W1[ff * HID + t];
            const float4* p = reinterpret_cast<const float4*>(&fSt[ff * MLP_SEQS]);
            float4 v0 = p[0], v1 = p[1], v2 = p[2], v3 = p[3];
            a[0]  = fmaf(v0.x, w, a[0]);  a[1]  = fmaf(v0.y, w, a[1]);
            a[2]  = fmaf(v0.z, w, a[2]);  a[3]  = fmaf(v0.w, w, a[3]);
            a[4]  = fmaf(v1.x, w, a[4]);  a[5]  = fmaf(v1.y, w, a[5]);
            a[6]  = fmaf(v1.z, w, a[6]);  a[7]  = fmaf(v1.w, w, a[7]);
            a[8]  = fmaf(v2.x, w, a[8]);  a[9]  = fmaf(v2.y, w, a[9]);
            a[10] = fmaf(v2.z, w, a[10]); a[11] = fmaf(v2.w, w, a[11]);
            a[12] = fmaf(v3.x, w, a[12]); a[13] = fmaf(v3.y, w, a[13]);
            a[14] = fmaf(v3.z, w, a[14]); a[15] = fmaf(v3.w, w, a[15]);
        }
        float4* q4 = reinterpret_cast<float4*>(&t1S[t * MLP_SEQS]);
#pragma unroll
        for (int q = 0; q < 4; ++q)
            q4[q] = make_float4(fmaxf(a[q * 4 + 0], 0.f), fmaxf(a[q * 4 + 1], 0.f),
                                fmaxf(a[q * 4 + 2], 0.f), fmaxf(a[q * 4 + 3], 0.f));
    }
    cp_async_wait_all();
    __syncthreads();

    // ---- Layer 2 (128 -> 128): 16 FMA per W2 shared load ----
    {
        float c[MLP_SEQS];
#pragma unroll
        for (int q = 0; q < MLP_SEQS; ++q) c[q] = 0.f;
#pragma unroll 4
        for (int h = 0; h < HID; ++h) {
            float w = W2s[h * HID + t];
            const float4* p = reinterpret_cast<const float4*>(&t1S[h * MLP_SEQS]);
            float4 v0 = p[0], v1 = p[1], v2 = p[2], v3 = p[3];
            c[0]  = fmaf(v0.x, w, c[0]);  c[1]  = fmaf(v0.y, w, c[1]);
            c[2]  = fmaf(v0.z, w, c[2]);  c[3]  = fmaf(v0.w, w, c[3]);
            c[4]  = fmaf(v1.x, w, c[4]);  c[5]  = fmaf(v1.y, w, c[5]);
            c[6]  = fmaf(v1.z, w, c[6]);  c[7]  = fmaf(v1.w, w, c[7]);
            c[8]  = fmaf(v2.x, w, c[8]);  c[9]  = fmaf(v2.y, w, c[9]);
            c[10] = fmaf(v2.z, w, c[10]); c[11] = fmaf(v2.w, w, c[11]);
            c[12] = fmaf(v3.x, w, c[12]); c[13] = fmaf(v3.y, w, c[13]);
            c[14] = fmaf(v3.z, w, c[14]); c[15] = fmaf(v3.w, w, c[15]);
        }
        float b = b2[t];
        float4* q4 = reinterpret_cast<float4*>(&t2S[t * MLP_SEQS]);
#pragma unroll
        for (int q = 0; q < 4; ++q)
            q4[q] = make_float4(fmaxf(c[q * 4 + 0] + b, 0.f), fmaxf(c[q * 4 + 1] + b, 0.f),
                                fmaxf(c[q * 4 + 2] + b, 0.f), fmaxf(c[q * 4 + 3] + b, 0.f));
    }
    __syncthreads();

    // ---- Logits + softmax: warp w (0..3) handles seqs s0+4w .. s0+4w+3 ----
    const int wid  = t >> 5;
    const int lane = t & 31;
#pragma unroll
    for (int p = 0; p < 4; ++p) {
        const int sq = wid * 4 + p;
        float acc[NCLS];
#pragma unroll
        for (int c = 0; c < NCLS; ++c) acc[c] = 0.f;
#pragma unroll
        for (int q = 0; q < 4; ++q) {
            int h = lane + q * 32;
            float v = t2S[h * MLP_SEQS + sq];
#pragma unroll
            for (int c = 0; c < NCLS; ++c) acc[c] = fmaf(v, WlS[c * HID + h], acc[c]);
        }
#pragma unroll
        for (int off = 16; off > 0; off >>= 1) {
#pragma unroll
            for (int c = 0; c < NCLS; ++c)
                acc[c] += __shfl_xor_sync(0xffffffffu, acc[c], off);
        }
        if (lane == 0) {
            float mx = -__int_as_float(0x7f800000);
#pragma unroll
            for (int c = 0; c < NCLS; ++c) {
                acc[c] += bl[c];
                mx = fmaxf(mx, acc[c]);
            }
            float e[NCLS];
            float sum = 0.f;
#pragma unroll
            for (int c = 0; c < NCLS; ++c) {
                e[c] = __expf(acc[c] - mx);
                sum += e[c];
            }
            float inv = 1.f / sum;
#pragma unroll
            for (int c = 0; c < NCLS; ++c)
                out[(s0 + sq) * NCLS + c] = e[c] * inv;
        }
    }
}

#define MLP_SMEM ((HID * HID + HID * MLP_SEQS + HID * MLP_SEQS + N_FILT * MLP_SEQS + HID * NCLS) * 4)

extern "C" void kernel_launch(void* const* d_in, const int* in_sizes, int n_in,
                              void* d_out, int out_size) {
    const float* x       = (const float*)d_in[0];
    const float* kernels = (const float*)d_in[1];
    const float* W1      = (const float*)d_in[2];
    const float* b1      = (const float*)d_in[3];
    const float* W2      = (const float*)d_in[4];
    const float* b2      = (const float*)d_in[5];
    const float* Wl      = (const float*)d_in[6];
    const float* bl      = (const float*)d_in[7];
    float* out = (float*)d_out;

    cudaFuncSetAttribute(mlp_kernel, cudaFuncAttributeMaxDynamicSharedMemorySize, MLP_SMEM);

    // Node 1: fused prep + DTW (plain launch).
    dtw_kernel<<<KM + N_SEQ, 32>>>(x, kernels);

    // Node 2: MLP, programmatic dependency on the fused kernel.
    {
        cudaLaunchConfig_t cfg = {};
        cfg.gridDim  = dim3(N_SEQ / MLP_SEQS, 1, 1);
        cfg.blockDim = dim3(128, 1, 1);
        cfg.dynamicSmemBytes = MLP_SMEM;
        cfg.stream = 0;
        cudaLaunchAttribute attr[1];
        attr[0].id = cudaLaunchAttributeProgrammaticStreamSerialization;
        attr[0].val.programmaticStreamSerializationAllowed = 1;
        cfg.attrs = attr;
        cfg.numAttrs = 1;
        cudaLaunchKernelEx(&cfg, mlp_kernel, W1, b1, W2, b2, Wl, bl, out);
    }
}